// round 8
// baseline (speedup 1.0000x reference)
#include <cuda_runtime.h>

#define D 128
#define TM 64           // gemm rows per block
#define N_NODES 100000
#define EPW 4           // edges per warp in edge kernel

// Quantized operands for the edge phase (halved gather bytes):
__device__ short g_z16[N_NODES * D];    // z, int16 row-scaled   (25.6 MB)
__device__ short g_wz16[N_NODES * D];   // wz, int16 row-scaled  (25.6 MB)
__device__ float g_sz[N_NODES];         // per-row scale of z
__device__ float g_sw[N_NODES];         // per-row scale of wz
__device__ int   g_idx64;               // 1 if edge_index is int64

// Packed fp32x2 helpers
#define PACK2(out, lo, hi) \
    asm("mov.b64 %0, {%1, %2};" : "=l"(out) : "f"(lo), "f"(hi))
#define UNPACK2(lo, hi, in) \
    asm("mov.b64 {%0, %1}, %2;" : "=f"(lo), "=f"(hi) : "l"(in))
#define FMA2(acc, a, b) \
    asm("fma.rn.f32x2 %0, %1, %2, %0;" : "+l"(acc) : "l"(a), "l"(b))

__device__ __forceinline__ short q15(float v, float inv) {
    int q = __float2int_rn(v * inv);
    q = max(-32767, min(32767, q));
    return (short)q;
}

// ---------------------------------------------------------------------------
// GEMM + both quantizations.
//   wz[n][o] = sum_k z[n][k]*W[o][k] + b[o]  -> int16 row-scaled g_wz16/g_sw
//   z[n]                                     -> int16 row-scaled g_z16/g_sz
// 256 threads, 64 rows x 128 cols per block, thread tile 8 rows x 4 cols,
// inner loop in fma.rn.f32x2 over row pairs (packed-pipe, 2 FMAs/instr).
// z-quant epilogue: warp w owns rows w*8..w*8+7, re-reads them from gmem
// (L2-hot right after the fill), butterfly row-max, quantize. This avoids the
// 16-way LDS conflicts a k-major shZ row-gather would cost.
// Block 0 thread 0 detects edge_index width (int64 samples all lie in [0,N);
// int32 read as int64 packs two indices and only looks valid when the high
// half is 0, p~1e-5/sample; 64 samples -> certain). Deterministic.
// ---------------------------------------------------------------------------
__global__ void __launch_bounds__(256, 2) gemm_kernel(const float* __restrict__ z,
                                                      const float* __restrict__ W,
                                                      const float* __restrict__ b,
                                                      const long long* __restrict__ ei64,
                                                      int E, int n_rows) {
    extern __shared__ float sh[];
    float* shW = sh;                 // [128][132] k-major
    float* shZ = sh + D * 132;       // [128][68]  k-major

    const int t = threadIdx.x;
    const int row0 = blockIdx.x * TM;

    if (blockIdx.x == 0 && t == 0) {
        int all_valid = 1;
        const int step = E > 64 ? E / 64 : 1;
        for (int i = 0; i < 64; i++) {
            long long v = ei64[(long long)(i * step) % E];
            if (v < 0 || v >= N_NODES) { all_valid = 0; break; }
        }
        g_idx64 = all_valid;
    }

    #pragma unroll 8
    for (int i = 0; i < D * D / 256; i++) {
        const int idx = t + i * 256;
        shW[(idx & 127) * 132 + (idx >> 7)] = W[idx];
    }
    #pragma unroll 8
    for (int i = 0; i < TM * D / 256; i++) {
        const int idx = t + i * 256;
        const int r = idx >> 7, k = idx & 127;
        int row = row0 + r; if (row >= n_rows) row = n_rows - 1;
        shZ[k * 68 + r] = z[(size_t)row * D + k];
    }
    __syncthreads();

    const int lane = t & 31;
    const int c0 = lane * 4;         // 4 output cols
    const int wrp = t >> 5;
    const int r0 = wrp * 8;          // 8 output rows (4 packed pairs)

    unsigned long long acc2[4][4];
    #pragma unroll
    for (int rp = 0; rp < 4; rp++)
        #pragma unroll
        for (int c = 0; c < 4; c++) acc2[rp][c] = 0ull;

    #pragma unroll 4
    for (int k = 0; k < D; k++) {
        const float4 wv = *(const float4*)&shW[k * 132 + c0];
        const float4 z0 = *(const float4*)&shZ[k * 68 + r0];
        const float4 z1 = *(const float4*)&shZ[k * 68 + r0 + 4];

        unsigned long long ww[4], zp[4];
        PACK2(ww[0], wv.x, wv.x);
        PACK2(ww[1], wv.y, wv.y);
        PACK2(ww[2], wv.z, wv.z);
        PACK2(ww[3], wv.w, wv.w);
        PACK2(zp[0], z0.x, z0.y);
        PACK2(zp[1], z0.z, z0.w);
        PACK2(zp[2], z1.x, z1.y);
        PACK2(zp[3], z1.z, z1.w);

        #pragma unroll
        for (int rp = 0; rp < 4; rp++) {
            FMA2(acc2[rp][0], zp[rp], ww[0]);
            FMA2(acc2[rp][1], zp[rp], ww[1]);
            FMA2(acc2[rp][2], zp[rp], ww[2]);
            FMA2(acc2[rp][3], zp[rp], ww[3]);
        }
    }

    // --- wz epilogue: bias, per-row warp max, int16 quantize ---
    const float4 bv = *(const float4*)&b[c0];
    float vals[8][4];
    #pragma unroll
    for (int rp = 0; rp < 4; rp++) {
        float lo[4], hi[4];
        #pragma unroll
        for (int c = 0; c < 4; c++) UNPACK2(lo[c], hi[c], acc2[rp][c]);
        vals[2 * rp][0] = lo[0] + bv.x; vals[2 * rp][1] = lo[1] + bv.y;
        vals[2 * rp][2] = lo[2] + bv.z; vals[2 * rp][3] = lo[3] + bv.w;
        vals[2 * rp + 1][0] = hi[0] + bv.x; vals[2 * rp + 1][1] = hi[1] + bv.y;
        vals[2 * rp + 1][2] = hi[2] + bv.z; vals[2 * rp + 1][3] = hi[3] + bv.w;
    }

    #pragma unroll
    for (int r = 0; r < 8; r++) {
        float m = fmaxf(fmaxf(fabsf(vals[r][0]), fabsf(vals[r][1])),
                        fmaxf(fabsf(vals[r][2]), fabsf(vals[r][3])));
        #pragma unroll
        for (int off = 16; off > 0; off >>= 1)
            m = fmaxf(m, __shfl_xor_sync(0xffffffffu, m, off));

        const float inv = 32767.0f / fmaxf(m, 1e-30f);
        const int row = row0 + r0 + r;
        if (row < n_rows) {
            short4 q;
            q.x = q15(vals[r][0], inv); q.y = q15(vals[r][1], inv);
            q.z = q15(vals[r][2], inv); q.w = q15(vals[r][3], inv);
            *(short4*)&g_wz16[(size_t)row * D + c0] = q;
            if (lane == 0) g_sw[row] = m * (1.0f / 32767.0f);
        }
    }

    // --- z epilogue: warp-per-row re-read from gmem (L2-hot), quantize ---
    #pragma unroll
    for (int r = 0; r < 8; r++) {
        const int row = row0 + wrp * 8 + r;
        if (row >= n_rows) break;

        const float4 v = ((const float4*)(z + (size_t)row * D))[lane];
        float m = fmaxf(fmaxf(fabsf(v.x), fabsf(v.y)), fmaxf(fabsf(v.z), fabsf(v.w)));
        #pragma unroll
        for (int off = 16; off > 0; off >>= 1)
            m = fmaxf(m, __shfl_xor_sync(0xffffffffu, m, off));

        const float inv = 32767.0f / fmaxf(m, 1e-30f);
        short4 q;
        q.x = q15(v.x, inv); q.y = q15(v.y, inv);
        q.z = q15(v.z, inv); q.w = q15(v.w, inv);
        ((short4*)(g_z16 + (size_t)row * D))[lane] = q;
        if (lane == 0) g_sz[row] = m * (1.0f / 32767.0f);
    }
}

// ---------------------------------------------------------------------------
// Edge compute: out[e] = sigmoid( sz[src]*sw[dst] * dot(z16[src], wz16[dst]) )
// One warp handles 4 edges; lane l loads short4 l of each 128-int16 row
// (256 B row, fully coalesced LDG.64). Scales prefetched by lanes 0..3.
// ---------------------------------------------------------------------------
__global__ void __launch_bounds__(512) edge_kernel(const void* __restrict__ ei_raw,
                                                   float* __restrict__ out,
                                                   int E) {
    const int warp = (int)((blockIdx.x * 512u + threadIdx.x) >> 5);
    const int lane = threadIdx.x & 31;
    const long long e0 = (long long)warp * EPW;
    if (e0 >= E) return;

    int src[EPW], dst[EPW];
    if (g_idx64) {
        const long long* ei = (const long long*)ei_raw;
        #pragma unroll
        for (int k = 0; k < EPW; k++) {
            long long e = e0 + k; if (e >= E) e = E - 1;
            src[k] = (int)ei[e];
            dst[k] = (int)ei[(long long)E + e];
        }
    } else {
        const int* ei = (const int*)ei_raw;
        #pragma unroll
        for (int k = 0; k < EPW; k++) {
            long long e = e0 + k; if (e >= E) e = E - 1;
            src[k] = ei[e];
            dst[k] = ei[E + e];
        }
    }

    float sc = 0.0f;
    if (lane < EPW)
        sc = g_sz[src[lane]] * g_sw[dst[lane]];

    short4 a[EPW], w[EPW];
    #pragma unroll
    for (int k = 0; k < EPW; k++)
        a[k] = ((const short4*)(g_z16 + (size_t)src[k] * D))[lane];
    #pragma unroll
    for (int k = 0; k < EPW; k++)
        w[k] = ((const short4*)(g_wz16 + (size_t)dst[k] * D))[lane];

    float v[EPW];
    #pragma unroll
    for (int k = 0; k < EPW; k++) {
        float s = (float)a[k].x * (float)w[k].x;
        s = fmaf((float)a[k].y, (float)w[k].y, s);
        s = fmaf((float)a[k].z, (float)w[k].z, s);
        s = fmaf((float)a[k].w, (float)w[k].w, s);
        v[k] = s;
    }

    #pragma unroll
    for (int off = 16; off > 0; off >>= 1) {
        #pragma unroll
        for (int k = 0; k < EPW; k++)
            v[k] += __shfl_xor_sync(0xffffffffu, v[k], off);
    }

    if (lane < EPW) {
        const float vv = (lane == 0) ? v[0] : (lane == 1) ? v[1] : (lane == 2) ? v[2] : v[3];
        const long long e = e0 + lane;
        if (e < E)
            out[e] = 1.0f / (1.0f + __expf(-vv * sc));
    }
}

// ---------------------------------------------------------------------------
// Launch. Inputs: z [N*D f32], edge_index [2*E int32-or-int64], W [D*D], b [D].
// Output: [E] f32.
// ---------------------------------------------------------------------------
extern "C" void kernel_launch(void* const* d_in, const int* in_sizes, int n_in,
                              void* d_out, int out_size) {
    const float* z  = (const float*)d_in[0];
    const void*  ei = d_in[1];
    const float* W  = (const float*)d_in[2];
    const float* b  = (const float*)d_in[3];
    float* out = (float*)d_out;

    const int E = out_size;
    const int n_rows = in_sizes[0] / D;

    const int smem = (D * 132 + D * 68) * (int)sizeof(float);   // ~102.4 KB
    cudaFuncSetAttribute(gemm_kernel, cudaFuncAttributeMaxDynamicSharedMemorySize, smem);
    gemm_kernel<<<(n_rows + TM - 1) / TM, 256, smem>>>(z, W, b,
                                                       (const long long*)ei, E, n_rows);

    const int warps_needed = (E + EPW - 1) / EPW;
    const int blocks = (warps_needed + 15) / 16;   // 16 warps (512 thr) per block
    edge_kernel<<<blocks, 512>>>(ei, out, E);
}

// round 9
// speedup vs baseline: 1.1284x; 1.1284x over previous
#include <cuda_runtime.h>

#define D 128
#define TM 64           // gemm rows per block
#define N_NODES 100000

// Quantized operands for the edge phase (halved gather bytes):
__device__ short g_z16[N_NODES * D];    // z, int16 row-scaled   (25.6 MB)
__device__ short g_wz16[N_NODES * D];   // wz, int16 row-scaled  (25.6 MB)
__device__ float g_sz[N_NODES];         // per-row scale of z
__device__ float g_sw[N_NODES];         // per-row scale of wz
__device__ int   g_idx64;               // 1 if edge_index is int64

// Packed fp32x2 helpers
#define PACK2(out, lo, hi) \
    asm("mov.b64 %0, {%1, %2};" : "=l"(out) : "f"(lo), "f"(hi))
#define UNPACK2(lo, hi, in) \
    asm("mov.b64 {%0, %1}, %2;" : "=f"(lo), "=f"(hi) : "l"(in))
#define FMA2(acc, a, b) \
    asm("fma.rn.f32x2 %0, %1, %2, %0;" : "+l"(acc) : "l"(a), "l"(b))

__device__ __forceinline__ short q15(float v, float inv) {
    int q = __float2int_rn(v * inv);
    q = max(-32767, min(32767, q));
    return (short)q;
}

// ---------------------------------------------------------------------------
// z quantization: one warp per row (butterfly row-max, int15 scale).
// Block 0 thread 0 also detects edge_index width (int64 samples all lie in
// [0,N); int32 read as int64 packs two indices and only looks valid when the
// high half is 0, p~1e-5/sample; 64 samples -> certain). Deterministic.
// ---------------------------------------------------------------------------
__global__ void __launch_bounds__(256) zquant_kernel(const float* __restrict__ z,
                                                     const long long* __restrict__ ei64,
                                                     int E, int n_rows) {
    if (blockIdx.x == 0 && threadIdx.x == 0) {
        int all_valid = 1;
        const int step = E > 64 ? E / 64 : 1;
        for (int i = 0; i < 64; i++) {
            long long v = ei64[(long long)(i * step) % E];
            if (v < 0 || v >= N_NODES) { all_valid = 0; break; }
        }
        g_idx64 = all_valid;
    }

    const int row = (int)((blockIdx.x * 256u + threadIdx.x) >> 5);
    const int lane = threadIdx.x & 31;
    if (row >= n_rows) return;

    const float4 v = ((const float4*)(z + (size_t)row * D))[lane];
    float m = fmaxf(fmaxf(fabsf(v.x), fabsf(v.y)), fmaxf(fabsf(v.z), fabsf(v.w)));
    #pragma unroll
    for (int off = 16; off > 0; off >>= 1)
        m = fmaxf(m, __shfl_xor_sync(0xffffffffu, m, off));

    const float inv = 32767.0f / fmaxf(m, 1e-30f);
    short4 q;
    q.x = q15(v.x, inv); q.y = q15(v.y, inv);
    q.z = q15(v.z, inv); q.w = q15(v.w, inv);
    ((short4*)(g_z16 + (size_t)row * D))[lane] = q;
    if (lane == 0) g_sz[row] = m * (1.0f / 32767.0f);
}

// ---------------------------------------------------------------------------
// GEMM: wz[n][o] = sum_k z[n][k]*W[o][k] + b[o], epilogue quantizes rows to
// int16. 256 threads, 64x128 per block, thread tile 8x4, fma.rn.f32x2 inner
// loop over row pairs.
// ---------------------------------------------------------------------------
__global__ void __launch_bounds__(256, 2) gemm_kernel(const float* __restrict__ z,
                                                      const float* __restrict__ W,
                                                      const float* __restrict__ b,
                                                      int n_rows) {
    extern __shared__ float sh[];
    float* shW = sh;                 // [128][132] k-major
    float* shZ = sh + D * 132;       // [128][68]  k-major

    const int t = threadIdx.x;
    const int row0 = blockIdx.x * TM;

    #pragma unroll 8
    for (int i = 0; i < D * D / 256; i++) {
        const int idx = t + i * 256;
        shW[(idx & 127) * 132 + (idx >> 7)] = W[idx];
    }
    #pragma unroll 8
    for (int i = 0; i < TM * D / 256; i++) {
        const int idx = t + i * 256;
        const int r = idx >> 7, k = idx & 127;
        int row = row0 + r; if (row >= n_rows) row = n_rows - 1;
        shZ[k * 68 + r] = z[(size_t)row * D + k];
    }
    __syncthreads();

    const int lane = t & 31;
    const int c0 = lane * 4;
    const int r0 = (t >> 5) * 8;

    unsigned long long acc2[4][4];
    #pragma unroll
    for (int rp = 0; rp < 4; rp++)
        #pragma unroll
        for (int c = 0; c < 4; c++) acc2[rp][c] = 0ull;

    #pragma unroll 4
    for (int k = 0; k < D; k++) {
        const float4 wv = *(const float4*)&shW[k * 132 + c0];
        const float4 z0 = *(const float4*)&shZ[k * 68 + r0];
        const float4 z1 = *(const float4*)&shZ[k * 68 + r0 + 4];

        unsigned long long ww[4], zp[4];
        PACK2(ww[0], wv.x, wv.x);
        PACK2(ww[1], wv.y, wv.y);
        PACK2(ww[2], wv.z, wv.z);
        PACK2(ww[3], wv.w, wv.w);
        PACK2(zp[0], z0.x, z0.y);
        PACK2(zp[1], z0.z, z0.w);
        PACK2(zp[2], z1.x, z1.y);
        PACK2(zp[3], z1.z, z1.w);

        #pragma unroll
        for (int rp = 0; rp < 4; rp++) {
            FMA2(acc2[rp][0], zp[rp], ww[0]);
            FMA2(acc2[rp][1], zp[rp], ww[1]);
            FMA2(acc2[rp][2], zp[rp], ww[2]);
            FMA2(acc2[rp][3], zp[rp], ww[3]);
        }
    }

    const float4 bv = *(const float4*)&b[c0];
    float vals[8][4];
    #pragma unroll
    for (int rp = 0; rp < 4; rp++) {
        float lo[4], hi[4];
        #pragma unroll
        for (int c = 0; c < 4; c++) UNPACK2(lo[c], hi[c], acc2[rp][c]);
        vals[2 * rp][0] = lo[0] + bv.x; vals[2 * rp][1] = lo[1] + bv.y;
        vals[2 * rp][2] = lo[2] + bv.z; vals[2 * rp][3] = lo[3] + bv.w;
        vals[2 * rp + 1][0] = hi[0] + bv.x; vals[2 * rp + 1][1] = hi[1] + bv.y;
        vals[2 * rp + 1][2] = hi[2] + bv.z; vals[2 * rp + 1][3] = hi[3] + bv.w;
    }

    #pragma unroll
    for (int r = 0; r < 8; r++) {
        float m = fmaxf(fmaxf(fabsf(vals[r][0]), fabsf(vals[r][1])),
                        fmaxf(fabsf(vals[r][2]), fabsf(vals[r][3])));
        #pragma unroll
        for (int off = 16; off > 0; off >>= 1)
            m = fmaxf(m, __shfl_xor_sync(0xffffffffu, m, off));

        const float inv = 32767.0f / fmaxf(m, 1e-30f);
        const int row = row0 + r0 + r;
        if (row < n_rows) {
            short4 q;
            q.x = q15(vals[r][0], inv); q.y = q15(vals[r][1], inv);
            q.z = q15(vals[r][2], inv); q.w = q15(vals[r][3], inv);
            *(short4*)&g_wz16[(size_t)row * D + c0] = q;
            if (lane == 0) g_sw[row] = m * (1.0f / 32767.0f);
        }
    }
}

// ---------------------------------------------------------------------------
// Edge compute: out[e] = sigmoid( sz[src]*sw[dst] * dot(z16[src], wz16[dst]) )
// 8 lanes per edge, 4 edges per warp. Each lane loads its 32 B row segment as
// 2x int4 (LDG.128); only 4 LDG.128 instructions move all 2 KB for the warp's
// 4 edges. The butterfly reduction is 3 levels (xor 4,2,1 within the 8-lane
// group) SHARED by all 4 edges -> 6 shfl/add per warp vs 40 in the 32-lane
// layout. Duplicate tail edges are clamped; stores guarded (same value ->
// deterministic).
// ---------------------------------------------------------------------------
__global__ void __launch_bounds__(512) edge_kernel(const void* __restrict__ ei_raw,
                                                   float* __restrict__ out,
                                                   int E) {
    const int warp = (int)((blockIdx.x * 512u + threadIdx.x) >> 5);
    const int lane = threadIdx.x & 31;
    const int sub  = lane >> 3;        // edge slot within warp (0..3)
    const int off  = lane & 7;         // segment within row (0..7)

    long long e = (long long)warp * 4 + sub;
    const long long e_clamped = e < E ? e : (long long)E - 1;

    int src, dst;
    if (g_idx64) {
        const long long* ei = (const long long*)ei_raw;
        src = (int)ei[e_clamped];
        dst = (int)ei[(long long)E + e_clamped];
    } else {
        const int* ei = (const int*)ei_raw;
        src = ei[e_clamped];
        dst = ei[E + e_clamped];
    }

    // Scales early (broadcast within the 8-lane group; 2 LDG.32 per warp).
    const float sc = g_sz[src] * g_sw[dst];

    const int4* za = (const int4*)(g_z16 + (size_t)src * D);   // 16 int4 per row
    const int4* wa = (const int4*)(g_wz16 + (size_t)dst * D);
    const int4 a0 = za[2 * off];
    const int4 a1 = za[2 * off + 1];
    const int4 w0 = wa[2 * off];
    const int4 w1 = wa[2 * off + 1];

    // dot of 16 int16 pairs (converted to f32; I2F.S16 H0/H1 selects)
    float s = 0.0f;
    #pragma unroll
    for (int p = 0; p < 4; p++) {
        const int av = (&a0.x)[p], wv = (&w0.x)[p];
        const short2 as = *(const short2*)&av;
        const short2 ws = *(const short2*)&wv;
        s = fmaf((float)as.x, (float)ws.x, s);
        s = fmaf((float)as.y, (float)ws.y, s);
    }
    #pragma unroll
    for (int p = 0; p < 4; p++) {
        const int av = (&a1.x)[p], wv = (&w1.x)[p];
        const short2 as = *(const short2*)&av;
        const short2 ws = *(const short2*)&wv;
        s = fmaf((float)as.x, (float)ws.x, s);
        s = fmaf((float)as.y, (float)ws.y, s);
    }

    // 3-level butterfly within each 8-lane group (serves all 4 edges at once)
    s += __shfl_xor_sync(0xffffffffu, s, 4);
    s += __shfl_xor_sync(0xffffffffu, s, 2);
    s += __shfl_xor_sync(0xffffffffu, s, 1);

    if (off == 0 && e < E)
        out[e] = 1.0f / (1.0f + __expf(-s * sc));
}

// ---------------------------------------------------------------------------
// Launch. Inputs: z [N*D f32], edge_index [2*E int32-or-int64], W [D*D], b [D].
// Output: [E] f32.
// ---------------------------------------------------------------------------
extern "C" void kernel_launch(void* const* d_in, const int* in_sizes, int n_in,
                              void* d_out, int out_size) {
    const float* z  = (const float*)d_in[0];
    const void*  ei = d_in[1];
    const float* W  = (const float*)d_in[2];
    const float* b  = (const float*)d_in[3];
    float* out = (float*)d_out;

    const int E = out_size;
    const int n_rows = in_sizes[0] / D;

    zquant_kernel<<<(n_rows * 32 + 255) / 256, 256>>>(z, (const long long*)ei, E, n_rows);

    const int smem = (D * 132 + D * 68) * (int)sizeof(float);   // ~102.4 KB
    cudaFuncSetAttribute(gemm_kernel, cudaFuncAttributeMaxDynamicSharedMemorySize, smem);
    gemm_kernel<<<(n_rows + TM - 1) / TM, 256, smem>>>(z, W, b, n_rows);

    const int warps_needed = (E + 3) / 4;               // 4 edges per warp
    const int blocks = (warps_needed + 15) / 16;        // 16 warps per block
    edge_kernel<<<blocks, 512>>>(ei, out, E);
}

// round 10
// speedup vs baseline: 1.2043x; 1.0672x over previous
#include <cuda_runtime.h>

#define D 128
#define TM 64           // gemm rows per block
#define N_NODES 100000

// Quantized operands for the edge phase (halved gather bytes):
__device__ short g_z16[N_NODES * D];    // z, int16 row-scaled   (25.6 MB)
__device__ short g_wz16[N_NODES * D];   // wz, int16 row-scaled  (25.6 MB)
__device__ float g_sz[N_NODES];         // per-row scale of z
__device__ float g_sw[N_NODES];         // per-row scale of wz
__device__ int   g_idx64;               // 1 if edge_index is int64

// Packed fp32x2 helpers
#define PACK2(out, lo, hi) \
    asm("mov.b64 %0, {%1, %2};" : "=l"(out) : "f"(lo), "f"(hi))
#define UNPACK2(lo, hi, in) \
    asm("mov.b64 {%0, %1}, %2;" : "=f"(lo), "=f"(hi) : "l"(in))
#define FMA2(acc, a, b) \
    asm("fma.rn.f32x2 %0, %1, %2, %0;" : "+l"(acc) : "l"(a), "l"(b))

// dp4a variants (mixed signedness for the int16 -> 2x int8 decomposition)
#define DP4A_SS(acc, a, b) \
    asm("dp4a.s32.s32 %0, %1, %2, %0;" : "+r"(acc) : "r"(a), "r"(b))
#define DP4A_SU(acc, a, b) \
    asm("dp4a.s32.u32 %0, %1, %2, %0;" : "+r"(acc) : "r"(a), "r"(b))
#define DP4A_US(acc, a, b) \
    asm("dp4a.u32.s32 %0, %1, %2, %0;" : "+r"(acc) : "r"(a), "r"(b))
#define DP4A_UU(acc, a, b) \
    asm("dp4a.u32.u32 %0, %1, %2, %0;" : "+r"(acc) : "r"(a), "r"(b))
#define PRMT(out, a, b, sel) \
    asm("prmt.b32 %0, %1, %2, %3;" : "=r"(out) : "r"(a), "r"(b), "n"(sel))

__device__ __forceinline__ short q15(float v, float inv) {
    int q = __float2int_rn(v * inv);
    q = max(-32767, min(32767, q));
    return (short)q;
}

// ---------------------------------------------------------------------------
// z quantization: one warp per row (butterfly row-max, int15 scale).
// Block 0 thread 0 also detects edge_index width (int64 samples all lie in
// [0,N); int32 read as int64 packs two indices and only looks valid when the
// high half is 0, p~1e-5/sample; 64 samples -> certain). Deterministic.
// ---------------------------------------------------------------------------
__global__ void __launch_bounds__(256) zquant_kernel(const float* __restrict__ z,
                                                     const long long* __restrict__ ei64,
                                                     int E, int n_rows) {
    if (blockIdx.x == 0 && threadIdx.x == 0) {
        int all_valid = 1;
        const int step = E > 64 ? E / 64 : 1;
        for (int i = 0; i < 64; i++) {
            long long v = ei64[(long long)(i * step) % E];
            if (v < 0 || v >= N_NODES) { all_valid = 0; break; }
        }
        g_idx64 = all_valid;
    }

    const int row = (int)((blockIdx.x * 256u + threadIdx.x) >> 5);
    const int lane = threadIdx.x & 31;
    if (row >= n_rows) return;

    const float4 v = ((const float4*)(z + (size_t)row * D))[lane];
    float m = fmaxf(fmaxf(fabsf(v.x), fabsf(v.y)), fmaxf(fabsf(v.z), fabsf(v.w)));
    #pragma unroll
    for (int off = 16; off > 0; off >>= 1)
        m = fmaxf(m, __shfl_xor_sync(0xffffffffu, m, off));

    const float inv = 32767.0f / fmaxf(m, 1e-30f);
    short4 q;
    q.x = q15(v.x, inv); q.y = q15(v.y, inv);
    q.z = q15(v.z, inv); q.w = q15(v.w, inv);
    ((short4*)(g_z16 + (size_t)row * D))[lane] = q;
    if (lane == 0) g_sz[row] = m * (1.0f / 32767.0f);
}

// ---------------------------------------------------------------------------
// GEMM: wz[n][o] = sum_k z[n][k]*W[o][k] + b[o], epilogue quantizes rows to
// int16. 256 threads, 64x128 per block, thread tile 8x4, fma.rn.f32x2 inner
// loop over row pairs. z row-pairs are loaded directly as ulonglong2 (no
// mov.b64 packs); only the 4 w-broadcast packs remain per k.
// ---------------------------------------------------------------------------
__global__ void __launch_bounds__(256, 2) gemm_kernel(const float* __restrict__ z,
                                                      const float* __restrict__ W,
                                                      const float* __restrict__ b,
                                                      int n_rows) {
    extern __shared__ float sh[];
    float* shW = sh;                 // [128][132] k-major
    float* shZ = sh + D * 132;       // [128][68]  k-major

    const int t = threadIdx.x;
    const int row0 = blockIdx.x * TM;

    #pragma unroll 8
    for (int i = 0; i < D * D / 256; i++) {
        const int idx = t + i * 256;
        shW[(idx & 127) * 132 + (idx >> 7)] = W[idx];
    }
    #pragma unroll 8
    for (int i = 0; i < TM * D / 256; i++) {
        const int idx = t + i * 256;
        const int r = idx >> 7, k = idx & 127;
        int row = row0 + r; if (row >= n_rows) row = n_rows - 1;
        shZ[k * 68 + r] = z[(size_t)row * D + k];
    }
    __syncthreads();

    const int lane = t & 31;
    const int c0 = lane * 4;
    const int r0 = (t >> 5) * 8;

    unsigned long long acc2[4][4];
    #pragma unroll
    for (int rp = 0; rp < 4; rp++)
        #pragma unroll
        for (int c = 0; c < 4; c++) acc2[rp][c] = 0ull;

    #pragma unroll 4
    for (int k = 0; k < D; k++) {
        const float4 wv = *(const float4*)&shW[k * 132 + c0];
        // Direct 64-bit pair loads: (r0, r0+1), (r0+2, r0+3), ... adjacent in
        // the k-major row; 16B aligned (k*272 and r0*4 are 16-multiples).
        const ulonglong2 zA = *(const ulonglong2*)&shZ[k * 68 + r0];
        const ulonglong2 zB = *(const ulonglong2*)&shZ[k * 68 + r0 + 4];
        const unsigned long long zp[4] = {zA.x, zA.y, zB.x, zB.y};

        unsigned long long ww[4];
        PACK2(ww[0], wv.x, wv.x);
        PACK2(ww[1], wv.y, wv.y);
        PACK2(ww[2], wv.z, wv.z);
        PACK2(ww[3], wv.w, wv.w);

        #pragma unroll
        for (int rp = 0; rp < 4; rp++) {
            FMA2(acc2[rp][0], zp[rp], ww[0]);
            FMA2(acc2[rp][1], zp[rp], ww[1]);
            FMA2(acc2[rp][2], zp[rp], ww[2]);
            FMA2(acc2[rp][3], zp[rp], ww[3]);
        }
    }

    const float4 bv = *(const float4*)&b[c0];
    float vals[8][4];
    #pragma unroll
    for (int rp = 0; rp < 4; rp++) {
        float lo[4], hi[4];
        #pragma unroll
        for (int c = 0; c < 4; c++) UNPACK2(lo[c], hi[c], acc2[rp][c]);
        vals[2 * rp][0] = lo[0] + bv.x; vals[2 * rp][1] = lo[1] + bv.y;
        vals[2 * rp][2] = lo[2] + bv.z; vals[2 * rp][3] = lo[3] + bv.w;
        vals[2 * rp + 1][0] = hi[0] + bv.x; vals[2 * rp + 1][1] = hi[1] + bv.y;
        vals[2 * rp + 1][2] = hi[2] + bv.z; vals[2 * rp + 1][3] = hi[3] + bv.w;
    }

    #pragma unroll
    for (int r = 0; r < 8; r++) {
        float m = fmaxf(fmaxf(fabsf(vals[r][0]), fabsf(vals[r][1])),
                        fmaxf(fabsf(vals[r][2]), fabsf(vals[r][3])));
        #pragma unroll
        for (int off = 16; off > 0; off >>= 1)
            m = fmaxf(m, __shfl_xor_sync(0xffffffffu, m, off));

        const float inv = 32767.0f / fmaxf(m, 1e-30f);
        const int row = row0 + r0 + r;
        if (row < n_rows) {
            short4 q;
            q.x = q15(vals[r][0], inv); q.y = q15(vals[r][1], inv);
            q.z = q15(vals[r][2], inv); q.w = q15(vals[r][3], inv);
            *(short4*)&g_wz16[(size_t)row * D + c0] = q;
            if (lane == 0) g_sw[row] = m * (1.0f / 32767.0f);
        }
    }
}

// ---------------------------------------------------------------------------
// Edge compute: out[e] = sigmoid( sz[src]*sw[dst] * dot(z16[src], wz16[dst]) )
// 8 lanes per edge, 4 edges per warp; lane loads its 32 B segment as 2x
// LDG.128. int16 dot via int8 decomposition:
//   a*b = 65536*ah*bh + 256*(ah*bl + al*bh) + al*bl
// with ah signed hi byte, al unsigned lo byte -- PRMT splits, 4 dp4a chains
// per int32 pair, exact integer partials, one fp32 combine per lane.
// ---------------------------------------------------------------------------
__global__ void __launch_bounds__(512) edge_kernel(const void* __restrict__ ei_raw,
                                                   float* __restrict__ out,
                                                   int E) {
    const int warp = (int)((blockIdx.x * 512u + threadIdx.x) >> 5);
    const int lane = threadIdx.x & 31;
    const int sub  = lane >> 3;        // edge slot within warp (0..3)
    const int off  = lane & 7;         // segment within row (0..7)

    long long e = (long long)warp * 4 + sub;
    const long long e_clamped = e < E ? e : (long long)E - 1;

    int src, dst;
    if (g_idx64) {
        const long long* ei = (const long long*)ei_raw;
        src = (int)ei[e_clamped];
        dst = (int)ei[(long long)E + e_clamped];
    } else {
        const int* ei = (const int*)ei_raw;
        src = ei[e_clamped];
        dst = ei[E + e_clamped];
    }

    const float sc = g_sz[src] * g_sw[dst];

    const int4* za = (const int4*)(g_z16 + (size_t)src * D);   // 16 int4 per row
    const int4* wa = (const int4*)(g_wz16 + (size_t)dst * D);
    const int4 a0 = za[2 * off];
    const int4 a1 = za[2 * off + 1];
    const int4 w0 = wa[2 * off];
    const int4 w1 = wa[2 * off + 1];

    // Split 16 int16 per operand into hi(signed)/lo(unsigned) byte planes.
    // reg bytes: [lo0 hi0 lo1 hi1]; pairwise PRMT -> 4 hi-plane + 4 lo-plane
    // regs per operand.
    const int areg[8] = {a0.x, a0.y, a0.z, a0.w, a1.x, a1.y, a1.z, a1.w};
    const int wreg[8] = {w0.x, w0.y, w0.z, w0.w, w1.x, w1.y, w1.z, w1.w};

    int hh = 0, hl = 0, lh = 0, ll = 0;
    #pragma unroll
    for (int p = 0; p < 4; p++) {
        int ah, al, bh, bl;
        PRMT(ah, areg[2 * p], areg[2 * p + 1], 0x7531);
        PRMT(al, areg[2 * p], areg[2 * p + 1], 0x6420);
        PRMT(bh, wreg[2 * p], wreg[2 * p + 1], 0x7531);
        PRMT(bl, wreg[2 * p], wreg[2 * p + 1], 0x6420);
        DP4A_SS(hh, ah, bh);
        DP4A_SU(hl, ah, bl);
        DP4A_US(lh, al, bh);
        DP4A_UU(ll, al, bl);
    }

    // Exact int partials -> fp32 combine (partials <= 2^20, no overflow).
    float s = 65536.0f * (float)hh;
    s = fmaf(256.0f, (float)(hl + lh), s);
    s += (float)ll;

    // 3-level butterfly within each 8-lane group (serves all 4 edges at once)
    s += __shfl_xor_sync(0xffffffffu, s, 4);
    s += __shfl_xor_sync(0xffffffffu, s, 2);
    s += __shfl_xor_sync(0xffffffffu, s, 1);

    if (off == 0 && e < E)
        out[e] = 1.0f / (1.0f + __expf(-s * sc));
}

// ---------------------------------------------------------------------------
// Launch. Inputs: z [N*D f32], edge_index [2*E int32-or-int64], W [D*D], b [D].
// Output: [E] f32.
// ---------------------------------------------------------------------------
extern "C" void kernel_launch(void* const* d_in, const int* in_sizes, int n_in,
                              void* d_out, int out_size) {
    const float* z  = (const float*)d_in[0];
    const void*  ei = d_in[1];
    const float* W  = (const float*)d_in[2];
    const float* b  = (const float*)d_in[3];
    float* out = (float*)d_out;

    const int E = out_size;
    const int n_rows = in_sizes[0] / D;

    zquant_kernel<<<(n_rows * 32 + 255) / 256, 256>>>(z, (const long long*)ei, E, n_rows);

    const int smem = (D * 132 + D * 68) * (int)sizeof(float);   // ~102.4 KB
    cudaFuncSetAttribute(gemm_kernel, cudaFuncAttributeMaxDynamicSharedMemorySize, smem);
    gemm_kernel<<<(n_rows + TM - 1) / TM, 256, smem>>>(z, W, b, n_rows);

    const int warps_needed = (E + 3) / 4;               // 4 edges per warp
    const int blocks = (warps_needed + 15) / 16;        // 16 warps per block
    edge_kernel<<<blocks, 512>>>(ei, out, E);
}